// round 1
// baseline (speedup 1.0000x reference)
#include <cuda_runtime.h>

// Problem constants
#define BB    64      // songs
#define FSPEC 128     // mel bins
#define TT    128     // frames
#define NPOS  16384
#define NNEG  16384   // B * NUM_NEG
#define TFEA  128     // text feature dim
#define DD    64      // embed dim

// Scratch (no allocs allowed): A [B,D,T] and projected rows PN [(NPOS+NNEG),D]
__device__ float g_A[BB * DD * TT];            // 2 MB
__device__ float g_PN[(NPOS + NNEG) * DD];     // 8 MB

// ---------------------------------------------------------------------------
// Kernel A: per-song projection  A[b] = Wa[64,128] @ spec[b][128,128]
// 1 block per b, 256 threads as 16x16, each thread 4(d) x 8(t) outputs.
// ---------------------------------------------------------------------------
__global__ void kA(const float* __restrict__ spec, const float* __restrict__ Wa) {
    extern __shared__ float sm[];
    float* sWa = sm;                 // [64][129]
    float* sSp = sm + 64 * 129;      // [128][132]  (132 keeps float4 alignment)

    const int b   = blockIdx.x;
    const int tid = threadIdx.x;

    for (int i = tid; i < DD * FSPEC; i += 256)
        sWa[(i / FSPEC) * 129 + (i % FSPEC)] = Wa[i];
    const float* sp = spec + b * FSPEC * TT;
    for (int i = tid; i < FSPEC * TT; i += 256)
        sSp[(i / TT) * 132 + (i % TT)] = sp[i];
    __syncthreads();

    const int tx = tid & 15, ty = tid >> 4;
    const int d0 = ty * 4, t0 = tx * 8;

    float acc[4][8];
#pragma unroll
    for (int i = 0; i < 4; i++)
#pragma unroll
        for (int j = 0; j < 8; j++) acc[i][j] = 0.f;

#pragma unroll 4
    for (int k = 0; k < FSPEC; k++) {
        float av[4];
#pragma unroll
        for (int i = 0; i < 4; i++) av[i] = sWa[(d0 + i) * 129 + k];
        float4 b0 = *(const float4*)&sSp[k * 132 + t0];
        float4 b1 = *(const float4*)&sSp[k * 132 + t0 + 4];
        float bv[8] = {b0.x, b0.y, b0.z, b0.w, b1.x, b1.y, b1.z, b1.w};
#pragma unroll
        for (int i = 0; i < 4; i++)
#pragma unroll
            for (int j = 0; j < 8; j++)
                acc[i][j] = fmaf(av[i], bv[j], acc[i][j]);
    }

#pragma unroll
    for (int i = 0; i < 4; i++) {
        float4 o0 = {acc[i][0], acc[i][1], acc[i][2], acc[i][3]};
        float4 o1 = {acc[i][4], acc[i][5], acc[i][6], acc[i][7]};
        float* dst = &g_A[(b * DD + d0 + i) * TT + t0];
        *(float4*)(dst)     = o0;
        *(float4*)(dst + 4) = o1;
    }
}

// ---------------------------------------------------------------------------
// Kernel P: text projection  PN[row] = X[row] @ Wt^T   (pos rows then neg rows)
// 128 rows per block, 256 threads: thread = 8(rows) x 4(d) outputs, K=128.
// ---------------------------------------------------------------------------
__global__ void kP(const float* __restrict__ pos, const float* __restrict__ neg,
                   const float* __restrict__ Wt) {
    extern __shared__ float sm[];
    float* sX  = sm;                 // [128][129]
    float* sWt = sm + 128 * 129;     // [64][129]

    const int tid     = threadIdx.x;
    const int rowbase = blockIdx.x * 128;
    const float* X = (rowbase < NPOS) ? (pos + rowbase * TFEA)
                                      : (neg + (rowbase - NPOS) * TFEA);

    for (int i = tid; i < 128 * TFEA; i += 256)
        sX[(i / TFEA) * 129 + (i % TFEA)] = X[i];
    for (int i = tid; i < DD * TFEA; i += 256)
        sWt[(i / TFEA) * 129 + (i % TFEA)] = Wt[i];
    __syncthreads();

    const int tx = tid & 15, ty = tid >> 4;
    const int r0 = ty * 8, c0 = tx * 4;

    float acc[8][4];
#pragma unroll
    for (int i = 0; i < 8; i++)
#pragma unroll
        for (int j = 0; j < 4; j++) acc[i][j] = 0.f;

#pragma unroll 4
    for (int k = 0; k < TFEA; k++) {
        float xv[8], wv[4];
#pragma unroll
        for (int i = 0; i < 8; i++) xv[i] = sX[(r0 + i) * 129 + k];
#pragma unroll
        for (int j = 0; j < 4; j++) wv[j] = sWt[(c0 + j) * 129 + k];
#pragma unroll
        for (int i = 0; i < 8; i++)
#pragma unroll
            for (int j = 0; j < 4; j++)
                acc[i][j] = fmaf(xv[i], wv[j], acc[i][j]);
    }

#pragma unroll
    for (int i = 0; i < 8; i++) {
        float4 o = {acc[i][0], acc[i][1], acc[i][2], acc[i][3]};
        *(float4*)&g_PN[(rowbase + r0 + i) * DD + c0] = o;
    }
}

// ---------------------------------------------------------------------------
// Kernel QA: out[row] = PN[row] @ A[seg(row)]    K = 64, N = 128 cols (t)
// blocks 0..127   : pos tiles (seg from pos_seg, sorted -> run scan)
// blocks 128..255 : neg tiles (seg = row >> 8)
// Per segment run: stage A[seg] (64x128) in smem, compute rows of the run.
// Thread covers rows r+ty+16*i (i<8), cols tx*8..+7.
// ---------------------------------------------------------------------------
__global__ void kQA(const int* __restrict__ pos_seg, float* __restrict__ out) {
    extern __shared__ float sm[];
    float* sP = sm;                  // [128][65]
    float* sA = sm + 128 * 65;       // [64][132]
    __shared__ int sSeg[128];

    const int tid   = threadIdx.x;
    const int blk   = blockIdx.x;
    const bool isPos = (blk < 128);
    const int rowbase = isPos ? blk * 128 : (blk - 128) * 128;
    const int gRow    = isPos ? rowbase : (NPOS + rowbase);

    for (int i = tid; i < 128 * DD; i += 256) {
        int r = i >> 6, c = i & 63;
        sP[r * 65 + c] = g_PN[(gRow + r) * DD + c];
    }
    if (tid < 128)
        sSeg[tid] = isPos ? pos_seg[rowbase + tid] : ((rowbase + tid) >> 8);
    __syncthreads();

    float* outBase = out + (isPos ? 0 : NPOS * TT) + rowbase * TT;
    const int tx = tid & 15, ty = tid >> 4;
    const int t0 = tx * 8;

    int r = 0;
    while (r < 128) {
        const int s = sSeg[r];
        int e = r + 1;
        while (e < 128 && sSeg[e] == s) e++;

        __syncthreads();   // previous run finished reading sA
        const float* Ag = g_A + s * DD * TT;
        for (int i = tid; i < DD * TT; i += 256)
            sA[(i >> 7) * 132 + (i & 127)] = Ag[i];
        __syncthreads();

        float acc[8][8];
#pragma unroll
        for (int i = 0; i < 8; i++)
#pragma unroll
            for (int j = 0; j < 8; j++) acc[i][j] = 0.f;

#pragma unroll 4
        for (int k = 0; k < DD; k++) {
            float pv[8];
#pragma unroll
            for (int i = 0; i < 8; i++) {
                int rr = r + ty + 16 * i;
                rr = rr < 127 ? rr : 127;          // clamp (masked at store)
                pv[i] = sP[rr * 65 + k];
            }
            float4 a0 = *(const float4*)&sA[k * 132 + t0];
            float4 a1 = *(const float4*)&sA[k * 132 + t0 + 4];
            float av[8] = {a0.x, a0.y, a0.z, a0.w, a1.x, a1.y, a1.z, a1.w};
#pragma unroll
            for (int i = 0; i < 8; i++)
#pragma unroll
                for (int j = 0; j < 8; j++)
                    acc[i][j] = fmaf(pv[i], av[j], acc[i][j]);
        }

#pragma unroll
        for (int i = 0; i < 8; i++) {
            int rr = r + ty + 16 * i;
            if (rr < e) {
                float4 o0 = {acc[i][0], acc[i][1], acc[i][2], acc[i][3]};
                float4 o1 = {acc[i][4], acc[i][5], acc[i][6], acc[i][7]};
                float* dst = &outBase[rr * TT + t0];
                *(float4*)(dst)     = o0;
                *(float4*)(dst + 4) = o1;
            }
        }
        r = e;
    }
}

// ---------------------------------------------------------------------------
extern "C" void kernel_launch(void* const* d_in, const int* in_sizes, int n_in,
                              void* d_out, int out_size) {
    const float* spec    = (const float*)d_in[0];
    const float* pos     = (const float*)d_in[1];
    const float* neg     = (const float*)d_in[2];
    const int*   pos_seg = (const int*)  d_in[3];
    const float* Wa      = (const float*)d_in[4];
    const float* Wt      = (const float*)d_in[5];
    float* out = (float*)d_out;

    const int smemA  = (64 * 129 + 128 * 132) * 4;   // 100,608
    const int smemP  = (128 * 129 + 64 * 129) * 4;   //  99,072
    const int smemQA = (128 * 65 + 64 * 132) * 4;    //  67,072

    cudaFuncSetAttribute(kA,  cudaFuncAttributeMaxDynamicSharedMemorySize, smemA);
    cudaFuncSetAttribute(kP,  cudaFuncAttributeMaxDynamicSharedMemorySize, smemP);
    cudaFuncSetAttribute(kQA, cudaFuncAttributeMaxDynamicSharedMemorySize, smemQA);

    kA<<<BB, 256, smemA>>>(spec, Wa);
    kP<<<(NPOS + NNEG) / 128, 256, smemP>>>(pos, neg, Wt);
    kQA<<<256, 256, smemQA>>>(pos_seg, out);
}

// round 2
// speedup vs baseline: 1.2102x; 1.2102x over previous
#include <cuda_runtime.h>

// Problem constants
#define BB    64      // songs
#define FSPEC 128     // mel bins
#define TT    128     // frames
#define NPOS  16384
#define NNEG  16384   // B * NUM_NEG
#define TFEA  128     // text feature dim
#define DD    64      // embed dim

typedef unsigned long long ull;

// Scratch: A [B,D,T] and projected rows PN [(NPOS+NNEG),D]
__device__ float g_A[BB * DD * TT];            // 2 MB
__device__ float g_PN[(NPOS + NNEG) * DD];     // 8 MB

// ---------------------------------------------------------------------------
// Packed fp32x2 helpers (Blackwell sm_100+; exact fp32 semantics, 2x fma pipe)
// ---------------------------------------------------------------------------
__device__ __forceinline__ ull fma2(ull a, ull b, ull c) {
    ull d;
    asm("fma.rn.f32x2 %0, %1, %2, %3;" : "=l"(d) : "l"(a), "l"(b), "l"(c));
    return d;
}
__device__ __forceinline__ ull dup2(float v) {
    ull r;
    asm("mov.b64 %0, {%1, %1};" : "=l"(r) : "f"(v));
    return r;
}

// ---------------------------------------------------------------------------
// Fused kernel 1:
//   blocks [0, 256)  : kP  — PN[row] = X[row] @ Wt^T        (128-row tiles)
//   blocks [256, 512): kA  — A[b] = Wa @ spec[b]            (64d x 32t tiles)
// ---------------------------------------------------------------------------
__global__ void __launch_bounds__(256) kAP(
    const float* __restrict__ spec, const float* __restrict__ pos,
    const float* __restrict__ neg,  const float* __restrict__ Wa,
    const float* __restrict__ Wt)
{
    extern __shared__ float sm[];
    const int tid = threadIdx.x;
    const int blk = blockIdx.x;

    if (blk < 256) {
        // ---------------- kP: text projection ----------------
        float* sX   = sm;                 // [128][129]
        float* sWtT = sm + 128 * 129;     // [128][68]  (k-major, c contiguous)

        const int rowbase = blk * 128;
        const float* X = (rowbase < NPOS) ? (pos + rowbase * TFEA)
                                          : (neg + (rowbase - NPOS) * TFEA);

        for (int i = tid; i < 128 * TFEA; i += 256)
            sX[(i >> 7) * 129 + (i & 127)] = X[i];
        for (int i = tid; i < DD * TFEA; i += 256) {
            int c = i >> 7, k = i & 127;
            sWtT[k * 68 + c] = Wt[i];
        }
        __syncthreads();

        const int tx = tid & 15, ty = tid >> 4;
        const int r0 = ty * 8, c0 = tx * 4;

        ull acc[8][2];
#pragma unroll
        for (int i = 0; i < 8; i++) { acc[i][0] = 0ull; acc[i][1] = 0ull; }

#pragma unroll 4
        for (int k = 0; k < TFEA; k++) {
            ull xd[8];
#pragma unroll
            for (int i = 0; i < 8; i++) xd[i] = dup2(sX[(r0 + i) * 129 + k]);
            ulonglong2 w = *(const ulonglong2*)&sWtT[k * 68 + c0];
#pragma unroll
            for (int i = 0; i < 8; i++) {
                acc[i][0] = fma2(xd[i], w.x, acc[i][0]);
                acc[i][1] = fma2(xd[i], w.y, acc[i][1]);
            }
        }

#pragma unroll
        for (int i = 0; i < 8; i++) {
            ulonglong2 o; o.x = acc[i][0]; o.y = acc[i][1];
            *(ulonglong2*)&g_PN[(rowbase + r0 + i) * DD + c0] = o;
        }
    } else {
        // ---------------- kA: audio projection ----------------
        float* sWa = sm;                  // [64][129]
        float* sSp = sm + 64 * 129;       // [128][36]

        const int ab = blk - 256;
        const int b  = ab >> 2;           // song
        const int tq = ab & 3;            // t quarter (32 frames)

        for (int i = tid; i < DD * FSPEC; i += 256)
            sWa[(i >> 7) * 129 + (i & 127)] = Wa[i];
        const float* sp = spec + b * FSPEC * TT + tq * 32;
        for (int i = tid; i < FSPEC * 32; i += 256) {
            int k = i >> 5, c = i & 31;
            sSp[k * 36 + c] = sp[k * TT + c];
        }
        __syncthreads();

        const int tx = tid & 15, ty = tid >> 4;
        const int d0 = ty * 4, t0 = tx * 2;

        ull acc[4];
#pragma unroll
        for (int i = 0; i < 4; i++) acc[i] = 0ull;

#pragma unroll 8
        for (int k = 0; k < FSPEC; k++) {
            ull bp = *(const ull*)&sSp[k * 36 + t0];
#pragma unroll
            for (int i = 0; i < 4; i++)
                acc[i] = fma2(dup2(sWa[(d0 + i) * 129 + k]), bp, acc[i]);
        }

#pragma unroll
        for (int i = 0; i < 4; i++)
            *(ull*)&g_A[(b * DD + d0 + i) * TT + tq * 32 + t0] = acc[i];
    }
}

// ---------------------------------------------------------------------------
// Kernel QA: out[row] = PN[row] @ A[seg(row)]    K = 64, 128 cols (t)
// blocks 0..127   : pos tiles (sorted pos_seg -> run scan)
// blocks 128..255 : neg tiles (seg = row >> 8)
// ---------------------------------------------------------------------------
__global__ void __launch_bounds__(256) kQA(const int* __restrict__ pos_seg,
                                           float* __restrict__ out) {
    extern __shared__ float sm[];
    float* sP = sm;                  // [128][65]
    float* sA = sm + 128 * 65;       // [64][132]
    __shared__ int sSeg[128];

    const int tid = threadIdx.x;
    const int blk = blockIdx.x;
    const bool isPos = (blk < 128);
    const int rowbase = isPos ? blk * 128 : (blk - 128) * 128;
    const int gRow    = isPos ? rowbase : (NPOS + rowbase);

    for (int i = tid; i < 128 * DD; i += 256) {
        int r = i >> 6, c = i & 63;
        sP[r * 65 + c] = g_PN[(gRow + r) * DD + c];
    }
    if (tid < 128)
        sSeg[tid] = isPos ? pos_seg[rowbase + tid] : ((rowbase + tid) >> 8);
    __syncthreads();

    float* outBase = out + (isPos ? 0 : NPOS * TT) + rowbase * TT;
    const int tx = tid & 15, ty = tid >> 4;
    const int t0 = tx * 8;

    int r = 0;
    while (r < 128) {
        const int s = sSeg[r];
        int e = r + 1;
        while (e < 128 && sSeg[e] == s) e++;

        __syncthreads();   // previous run done reading sA
        const float* Ag = g_A + s * DD * TT;
        for (int i = tid; i < DD * TT; i += 256)
            sA[(i >> 7) * 132 + (i & 127)] = Ag[i];
        __syncthreads();

        ull acc[8][4];
#pragma unroll
        for (int i = 0; i < 8; i++)
#pragma unroll
            for (int j = 0; j < 4; j++) acc[i][j] = 0ull;

#pragma unroll 4
        for (int k = 0; k < DD; k++) {
            ull pd[8];
#pragma unroll
            for (int i = 0; i < 8; i++) {
                int rr = r + ty + 16 * i;
                rr = rr < 127 ? rr : 127;          // clamp (masked at store)
                pd[i] = dup2(sP[rr * 65 + k]);
            }
            ulonglong2 a01 = *(const ulonglong2*)&sA[k * 132 + t0];
            ulonglong2 a23 = *(const ulonglong2*)&sA[k * 132 + t0 + 4];
#pragma unroll
            for (int i = 0; i < 8; i++) {
                acc[i][0] = fma2(pd[i], a01.x, acc[i][0]);
                acc[i][1] = fma2(pd[i], a01.y, acc[i][1]);
                acc[i][2] = fma2(pd[i], a23.x, acc[i][2]);
                acc[i][3] = fma2(pd[i], a23.y, acc[i][3]);
            }
        }

#pragma unroll
        for (int i = 0; i < 8; i++) {
            int rr = r + ty + 16 * i;
            if (rr < e) {
                ulonglong2 o0; o0.x = acc[i][0]; o0.y = acc[i][1];
                ulonglong2 o1; o1.x = acc[i][2]; o1.y = acc[i][3];
                float* dst = &outBase[rr * TT + t0];
                *(ulonglong2*)(dst)     = o0;
                *(ulonglong2*)(dst + 4) = o1;
            }
        }
        r = e;
    }
}

// ---------------------------------------------------------------------------
extern "C" void kernel_launch(void* const* d_in, const int* in_sizes, int n_in,
                              void* d_out, int out_size) {
    const float* spec    = (const float*)d_in[0];
    const float* pos     = (const float*)d_in[1];
    const float* neg     = (const float*)d_in[2];
    const int*   pos_seg = (const int*)  d_in[3];
    const float* Wa      = (const float*)d_in[4];
    const float* Wt      = (const float*)d_in[5];
    float* out = (float*)d_out;

    const int smemAP = (128 * 129 + 128 * 68) * 4;   // 100,864 (kP shape, max)
    const int smemQA = (128 * 65 + 64 * 132) * 4;    //  67,072

    cudaFuncSetAttribute(kAP, cudaFuncAttributeMaxDynamicSharedMemorySize, smemAP);
    cudaFuncSetAttribute(kQA, cudaFuncAttributeMaxDynamicSharedMemorySize, smemQA);

    kAP<<<512, 256, smemAP>>>(spec, pos, neg, Wa, Wt);
    kQA<<<256, 256, smemQA>>>(pos_seg, out);
}